// round 10
// baseline (speedup 1.0000x reference)
#include <cuda_runtime.h>
#include <math.h>

#define HIDDEN 1024
#define NINTER 256
#define WINDOW 64
#define K1_BLOCKS 32
#define FIX_SCALE 281474976710656.0   // 2^48

// persistent state (allocation-free rule: __device__ globals)
// g_fix/g_ticket are monotonic across replays; per-replay values recovered by
// exact modular difference / mod-32 ticket -> no reset node required.
__device__ unsigned long long g_fix;    // fixed-point sum of tanh terms
__device__ unsigned long long g_base;   // snapshot of g_fix at last replay end
__device__ unsigned           g_ticket;
__device__ int4               g_head;   // {ws, we, et_bits, 0}

// fp64 exp, rel err ~1e-13 (range reduction + degree-9, Estrin form)
__device__ __forceinline__ double fast_exp(double x) {
    const double LOG2E  = 1.4426950408889634074;
    const double LN2_HI = 6.9314718055994528623e-1;
    const double LN2_LO = 2.3190468138462995584e-17;
    double n = rint(x * LOG2E);
    double r = fma(-n, LN2_HI, x);
    r = fma(-n, LN2_LO, r);
    double p01 = 1.0 + r;
    double p23 = fma(r, 1.6666666666666665741e-1, 5.0e-1);
    double p45 = fma(r, 8.3333333333333332177e-3, 4.1666666666666664354e-2);
    double p67 = fma(r, 1.9841269841269841253e-4, 1.3888888888888889419e-3);
    double p89 = fma(r, 2.7557319223985890653e-6, 2.4801587301587301566e-5);
    double r2 = r * r;
    double q0 = fma(r2, p23, p01);
    double q1 = fma(r2, p67, p45);
    double r4 = r2 * r2;
    double s0 = fma(r4, q1, q0);
    double r8 = r4 * r4;
    double res = fma(r8, p89, s0);
    long long ni = (long long)n;
    double sc = __longlong_as_double((ni + 1023LL) << 52);  // exact 2^n
    return res * sc;
}

// 1/d via fp32 rcp seed + 1 fp64 Newton step (rel err ~2^-44)
__device__ __forceinline__ double fast_recip(double d) {
    double y = (double)__frcp_rn((float)d);
    return y * fma(-d, y, 2.0);
}

// ---------------------------------------------------------------------------
// Kernel 1: 32 blocks x 8 warps, warp-per-row MLP (rows = 8*bid + wid).
// Each lane: 8 float4 of w + 8 float4 of h (one load batch), fp64 dot,
// fp32 warp reduce; lane0 -> tanhf*fc2_w -> exact fixed-point int.
// Block sums its 8 ints in smem (exact) -> ONE atomicAdd (32 total).
// Last block (mod-32 ticket) computes the exact head, publishes g_head.
// ---------------------------------------------------------------------------
__global__ void __launch_bounds__(256) mlp1_kernel(
        const float* __restrict__ ht,
        const float* __restrict__ fc1_w,
        const float* __restrict__ fc1_b,
        const float* __restrict__ fc2_w,
        const float* __restrict__ fc2_b, int S) {
    asm volatile("griddepcontrol.launch_dependents;" ::: "memory");

    const int tid  = threadIdx.x;
    const int lane = tid & 31;
    const int wid  = tid >> 5;
    const int bid  = blockIdx.x;
    const int row  = (bid << 3) + wid;

    __shared__ long long sfx[8];

    const float4* wp = (const float4*)(fc1_w + (size_t)row * HIDDEN);
    const float4* hp = (const float4*)ht;

    float4 w[8], h[8];
    #pragma unroll
    for (int j = 0; j < 8; j++) w[j] = wp[lane + (j << 5)];
    #pragma unroll
    for (int j = 0; j < 8; j++) h[j] = hp[lane + (j << 5)];

    double a0 = 0.0, a1 = 0.0, a2 = 0.0, a3 = 0.0;
    #pragma unroll
    for (int j = 0; j < 8; j++) {
        a0 = fma((double)w[j].x, (double)h[j].x, a0);
        a1 = fma((double)w[j].y, (double)h[j].y, a1);
        a2 = fma((double)w[j].z, (double)h[j].z, a2);
        a3 = fma((double)w[j].w, (double)h[j].w, a3);
    }
    float accf = (float)((a0 + a1) + (a2 + a3));
    #pragma unroll
    for (int o = 16; o > 0; o >>= 1)
        accf += __shfl_down_sync(0xffffffffu, accf, o);

    if (lane == 0) {
        float zf   = accf + fc1_b[row];
        float term = tanhf(zf) * fc2_w[row];
        sfx[wid] = __float2ll_rn(term * (float)FIX_SCALE);  // exact
    }
    __syncthreads();

    if (tid == 0) {
        long long fx = ((sfx[0] + sfx[1]) + (sfx[2] + sfx[3]))
                     + ((sfx[4] + sfx[5]) + (sfx[6] + sfx[7]));
        atomicAdd(&g_fix, (unsigned long long)fx);
        __threadfence();
        unsigned t = atomicAdd(&g_ticket, 1u);
        if (((t + 1u) & (K1_BLOCKS - 1u)) == 0u) {   // last block this replay
            unsigned long long cur  = atomicAdd(&g_fix, 0ULL);
            unsigned long long prev = atomicExch(&g_base, cur);
            long long diff = (long long)(cur - prev);    // exact modular diff
            double z  = (double)diff * (1.0 / FIX_SCALE) + (double)fc2_b[0];
            double e  = fast_exp(-z);
            double pt = (double)S * fast_recip(1.0 + e);
            // pt in (0,S), non-integer: ceil(pt-64)=floor(pt)-63,
            //                           floor(pt+64)=floor(pt)+64
            int k  = (int)pt;
            int ws = k - (WINDOW - 1);  if (ws < 0)     ws = 0;
            int we = k + WINDOW;        if (we > S - 1) we = S - 1;
            float et = __expf((float)(((double)S - pt) * (1.0 / 2048.0)));
            g_head = make_int4(ws, we, __float_as_int(et), 0);
        }
    }
}

// ---------------------------------------------------------------------------
// Kernel 2 (PDL dependent, unchanged from R9 @5.38us): minimal post-wait
// chain: wait -> 16B g_head load -> <=3 predicated window loads -> fp32
// shuffle + smem reduce -> scale by e_t -> store.
// ---------------------------------------------------------------------------
__global__ void __launch_bounds__(256) windowsum_kernel(
        const float* __restrict__ hs,
        float* __restrict__ out) {
    const int tid  = threadIdx.x;
    const int lane = tid & 31;
    const int wid  = tid >> 5;

    __shared__ float colsum[8][36];

    // prologue independent of K1 (overlaps K1 under PDL)
    const int col    = (blockIdx.x << 2) + (tid & 3);
    const int rowoff = tid >> 2;                     // 0..63
    const float* base = hs + col;

    asm volatile("griddepcontrol.wait;" ::: "memory");

    const int4 hd = __ldcg(&g_head);
    const int   ws = hd.x;
    const int   we = hd.y;
    const float et = __int_as_float(hd.z);

    const int r0 = ws + rowoff;
    const int r1 = r0 + 64;
    const int r2 = r0 + 128;

    float acc = 0.f;
    if (r0 <= we) acc += base[(size_t)r0 * HIDDEN];
    if (r1 <= we) acc += base[(size_t)r1 * HIDDEN];
    if (r2 <= we) acc += base[(size_t)r2 * HIDDEN];

    // fold the 8 rowgroups within each warp (keeps the 4 column lanes)
    #pragma unroll
    for (int o = 16; o >= 4; o >>= 1)
        acc += __shfl_xor_sync(0xffffffffu, acc, o);
    if (lane < 4) colsum[wid][lane] = acc;           // 8 warps x 4 cols
    __syncthreads();

    if (tid < 4) {
        float s = ((colsum[0][tid] + colsum[1][tid])
                 + (colsum[2][tid] + colsum[3][tid]))
                + ((colsum[4][tid] + colsum[5][tid])
                 + (colsum[6][tid] + colsum[7][tid]));
        out[col] = et * s;
    }
}

extern "C" void kernel_launch(void* const* d_in, const int* in_sizes, int n_in,
                              void* d_out, int out_size) {
    const float* hs    = (const float*)d_in[0];
    const float* ht    = (const float*)d_in[1];
    const float* fc1_w = (const float*)d_in[2];
    const float* fc1_b = (const float*)d_in[3];
    const float* fc2_w = (const float*)d_in[4];
    const float* fc2_b = (const float*)d_in[5];

    const int S = in_sizes[0] / HIDDEN;   // host-side constant, capture-safe

    mlp1_kernel<<<K1_BLOCKS, 256>>>(ht, fc1_w, fc1_b, fc2_w, fc2_b, S);

    // K2 as a PDL dependent launch
    cudaLaunchConfig_t cfg = {};
    cfg.gridDim  = dim3(NINTER, 1, 1);
    cfg.blockDim = dim3(256, 1, 1);
    cfg.dynamicSmemBytes = 0;
    cfg.stream = 0;
    cudaLaunchAttribute attr[1];
    attr[0].id = cudaLaunchAttributeProgrammaticStreamSerialization;
    attr[0].val.programmaticStreamSerializationAllowed = 1;
    cfg.attrs = attr;
    cfg.numAttrs = 1;
    float* outp = (float*)d_out;
    cudaLaunchKernelEx(&cfg, windowsum_kernel, hs, outp);
}

// round 11
// speedup vs baseline: 1.2535x; 1.2535x over previous
#include <cuda_runtime.h>
#include <math.h>

#define HIDDEN 1024
#define NINTER 256
#define WINDOW 64

// persistent state (allocation-free rule: __device__ globals).
// g_count/g_seq are monotonic across graph replays -> no reset nodes needed.
__device__ unsigned g_count;    // 256 REDG increments per replay
__device__ unsigned g_seq;      // replay epoch, written only by the head block
__device__ float    g_p[NINTER];
__device__ int4     g_headv;    // {ws, we, et_bits, 0}

// fp64 exp, rel err ~1e-13 (range reduction + degree-9, Estrin form)
__device__ __forceinline__ double fast_exp(double x) {
    const double LOG2E  = 1.4426950408889634074;
    const double LN2_HI = 6.9314718055994528623e-1;
    const double LN2_LO = 2.3190468138462995584e-17;
    double n = rint(x * LOG2E);
    double r = fma(-n, LN2_HI, x);
    r = fma(-n, LN2_LO, r);
    double p01 = 1.0 + r;
    double p23 = fma(r, 1.6666666666666665741e-1, 5.0e-1);
    double p45 = fma(r, 8.3333333333333332177e-3, 4.1666666666666664354e-2);
    double p67 = fma(r, 1.9841269841269841253e-4, 1.3888888888888889419e-3);
    double p89 = fma(r, 2.7557319223985890653e-6, 2.4801587301587301566e-5);
    double r2 = r * r;
    double q0 = fma(r2, p23, p01);
    double q1 = fma(r2, p67, p45);
    double r4 = r2 * r2;
    double s0 = fma(r4, q1, q0);
    double r8 = r4 * r4;
    double res = fma(r8, p89, s0);
    long long ni = (long long)n;
    double sc = __longlong_as_double((ni + 1023LL) << 52);  // exact 2^n
    return res * sc;
}

// 1/d via fp32 rcp seed + 1 fp64 Newton step (rel err ~2^-44)
__device__ __forceinline__ double fast_recip(double d) {
    double y = (double)__frcp_rn((float)d);
    return y * fma(-d, y, 2.0);
}

// ---------------------------------------------------------------------------
// ONE kernel, grid = 257 blocks x 256 threads (>=148: dodges low-grid throttle).
//
// Blocks 0..255 (stage A + C):
//   A: block b computes term_b = tanhf(dot_fp64(fc1_w[b,:],h_t)+fc1_b[b])*fc2_w[b],
//      stores g_p[b], threadfence, REDG-increments g_count (return unused).
//   tid0 polls g_seq until epoch advances, caches head in smem.
//   C: windowed row-sum for cols 4b..4b+3 (R9 shape: 3 predicated loads,
//      xor-shuffle + smem reduce).
// Block 256 (head only):
//   waits g_count >= 256*(R+1), reduces the 256 fp32 terms in fp64
//   (fixed shuffle order, deterministic), computes p_t/window/e_t,
//   publishes payload then g_seq = R+1.
//
// Deadlock-free by construction: waiters depend only on the head's publish;
// the head depends only on the 256 unconditional REDG increments. No cycle.
// Epoch read is race-free: the head cannot publish epoch R+1 before a stage-A
// block increments, and each block reads g_seq BEFORE its own increment.
// ---------------------------------------------------------------------------
__global__ void __launch_bounds__(256) fused_attn_kernel(
        const float* __restrict__ hs,
        const float* __restrict__ ht,
        const float* __restrict__ fc1_w,
        const float* __restrict__ fc1_b,
        const float* __restrict__ fc2_w,
        const float* __restrict__ fc2_b,
        float* __restrict__ out, int S) {
    const int tid  = threadIdx.x;
    const int lane = tid & 31;
    const int wid  = tid >> 5;
    const int bid  = blockIdx.x;

    // ------------------- head block -------------------
    if (bid == NINTER) {
        if (wid == 0) {
            unsigned R = *(volatile unsigned*)&g_seq;       // prev epoch
            unsigned target = (R + 1u) << 8;                // 256*(R+1)
            if (lane == 0) {
                while (*(volatile unsigned*)&g_count < target) { }
            }
            __syncwarp();
            __threadfence();                                // acquire g_p
            const float4* gp4 = (const float4*)g_p;
            float4 p0 = __ldcg(gp4 + (lane << 1));
            float4 p1 = __ldcg(gp4 + (lane << 1) + 1);
            double v = (((double)p0.x + (double)p0.y)
                      + ((double)p0.z + (double)p0.w))
                     + (((double)p1.x + (double)p1.y)
                      + ((double)p1.z + (double)p1.w));
            #pragma unroll
            for (int o = 16; o > 0; o >>= 1)
                v += __shfl_down_sync(0xffffffffu, v, o);
            if (lane == 0) {
                double z  = v + (double)fc2_b[0];
                double e  = fast_exp(-z);
                double pt = (double)S * fast_recip(1.0 + e);
                // pt in (0,S), non-integer: ceil(pt-64)=floor(pt)-63,
                //                           floor(pt+64)=floor(pt)+64
                int k  = (int)pt;
                int ws = k - (WINDOW - 1);  if (ws < 0)     ws = 0;
                int we = k + WINDOW;        if (we > S - 1) we = S - 1;
                float et = __expf((float)(((double)S - pt) * (1.0 / 2048.0)));
                g_headv = make_int4(ws, we, __float_as_int(et), 0);
                __threadfence();                            // payload first
                *(volatile unsigned*)&g_seq = R + 1u;       // then epoch
            }
        }
        return;
    }

    // ------------------- stage A: MLP row = bid -------------------
    __shared__ float sred[8];
    __shared__ int4  shead;

    float4 w = ((const float4*)(fc1_w + (size_t)bid * HIDDEN))[tid];
    float4 h = ((const float4*)ht)[tid];
    double e0 = fma((double)w.y, (double)h.y, (double)w.x * h.x);
    double e1 = fma((double)w.w, (double)h.w, (double)w.z * h.z);
    float accf = (float)(e0 + e1);
    #pragma unroll
    for (int o = 16; o > 0; o >>= 1)
        accf += __shfl_down_sync(0xffffffffu, accf, o);
    if (lane == 0) sred[wid] = accf;
    __syncthreads();

    if (tid == 0) {
        unsigned R = *(volatile unsigned*)&g_seq;           // BEFORE increment
        float zf = ((sred[0] + sred[1]) + (sred[2] + sred[3]))
                 + ((sred[4] + sred[5]) + (sred[6] + sred[7]))
                 + fc1_b[bid];
        g_p[bid] = tanhf(zf) * fc2_w[bid];
        __threadfence();
        atomicAdd(&g_count, 1u);                            // REDG (no return)
        while (*(volatile unsigned*)&g_seq < R + 1u) { }    // wait for head
        __threadfence();
        shead = __ldcg(&g_headv);
    }
    __syncthreads();

    // ------------------- stage C: windowed row-sum -------------------
    const int4  hd = shead;
    const int   ws = hd.x;
    const int   we = hd.y;
    const float et = __int_as_float(hd.z);

    const int col    = (bid << 2) + (tid & 3);
    const int rowoff = tid >> 2;                            // 0..63
    const float* base = hs + col;
    const int r0 = ws + rowoff;
    const int r1 = r0 + 64;
    const int r2 = r0 + 128;

    float acc = 0.f;
    if (r0 <= we) acc += base[(size_t)r0 * HIDDEN];
    if (r1 <= we) acc += base[(size_t)r1 * HIDDEN];
    if (r2 <= we) acc += base[(size_t)r2 * HIDDEN];

    // fold the 8 rowgroups within each warp (keeps the 4 column lanes)
    #pragma unroll
    for (int o = 16; o >= 4; o >>= 1)
        acc += __shfl_xor_sync(0xffffffffu, acc, o);

    __shared__ float colsum[8][36];
    if (lane < 4) colsum[wid][lane] = acc;                  // 8 warps x 4 cols
    __syncthreads();

    if (tid < 4) {
        float s = ((colsum[0][tid] + colsum[1][tid])
                 + (colsum[2][tid] + colsum[3][tid]))
                + ((colsum[4][tid] + colsum[5][tid])
                 + (colsum[6][tid] + colsum[7][tid]));
        out[col] = et * s;
    }
}

extern "C" void kernel_launch(void* const* d_in, const int* in_sizes, int n_in,
                              void* d_out, int out_size) {
    const float* hs    = (const float*)d_in[0];
    const float* ht    = (const float*)d_in[1];
    const float* fc1_w = (const float*)d_in[2];
    const float* fc1_b = (const float*)d_in[3];
    const float* fc2_w = (const float*)d_in[4];
    const float* fc2_b = (const float*)d_in[5];

    const int S = in_sizes[0] / HIDDEN;   // host-side constant, capture-safe

    fused_attn_kernel<<<NINTER + 1, 256>>>(hs, ht, fc1_w, fc1_b, fc2_w, fc2_b,
                                           (float*)d_out, S);
}

// round 12
// speedup vs baseline: 1.3842x; 1.1043x over previous
#include <cuda_runtime.h>
#include <math.h>

#define HIDDEN 1024
#define NINTER 256
#define WINDOW 64
#define PAD    8

// persistent state (allocation-free rule: __device__ globals).
// All counters monotonic across graph replays -> no reset nodes needed.
__device__ unsigned           g_count;     // 256 REDG increments per replay
__device__ unsigned long long g_seq_full;  // full-width epoch (head-only access)
__device__ unsigned long long g_est;       // {epoch15<<49 | est_lo17<<32}
__device__ unsigned long long g_exact;     // {epoch15<<49 | k17<<32 | et_bits32}
__device__ float              g_p[NINTER];

// fp64 exp, rel err ~1e-13 (range reduction + degree-9, Estrin form)
__device__ __forceinline__ double fast_exp(double x) {
    const double LOG2E  = 1.4426950408889634074;
    const double LN2_HI = 6.9314718055994528623e-1;
    const double LN2_LO = 2.3190468138462995584e-17;
    double n = rint(x * LOG2E);
    double r = fma(-n, LN2_HI, x);
    r = fma(-n, LN2_LO, r);
    double p01 = 1.0 + r;
    double p23 = fma(r, 1.6666666666666665741e-1, 5.0e-1);
    double p45 = fma(r, 8.3333333333333332177e-3, 4.1666666666666664354e-2);
    double p67 = fma(r, 1.9841269841269841253e-4, 1.3888888888888889419e-3);
    double p89 = fma(r, 2.7557319223985890653e-6, 2.4801587301587301566e-5);
    double r2 = r * r;
    double q0 = fma(r2, p23, p01);
    double q1 = fma(r2, p67, p45);
    double r4 = r2 * r2;
    double s0 = fma(r4, q1, q0);
    double r8 = r4 * r4;
    double res = fma(r8, p89, s0);
    long long ni = (long long)n;
    double sc = __longlong_as_double((ni + 1023LL) << 52);  // exact 2^n
    return res * sc;
}

// 1/d via fp32 rcp seed + 1 fp64 Newton step (rel err ~2^-44)
__device__ __forceinline__ double fast_recip(double d) {
    double y = (double)__frcp_rn((float)d);
    return y * fma(-d, y, 2.0);
}

// ---------------------------------------------------------------------------
// ONE kernel, grid = 257 x 256 (>=148: dodges the low-grid throttle).
//
// Block 0 = HEAD: waits for 256 REDG counts, fp32-reduces g_p, publishes a
//   fast fp32 ESTIMATE window base (one packed u64: epoch|est_lo), then the
//   EXACT fp64 head (epoch|k|et_bits). Single-word publishes: the waiters'
//   poll IS the payload read; no fences needed for the payload.
// Blocks 1..256 = row b-1: MLP term -> g_p, fence, REDG count; poll est word;
//   issue padded window loads (PAD=8 covers est error ~1e-3 rows); poll exact
//   word (lands under the loads); mask by exact [ws,we]; reduce; store.
//
// Deadlock-free: waiters depend only on head publishes; head depends only on
// the 256 unconditional REDG increments. Epoch read is race-free (read before
// own increment; head can't reach 256 counts before that).
// ---------------------------------------------------------------------------
__global__ void __launch_bounds__(256) fused_attn_kernel(
        const float* __restrict__ hs,
        const float* __restrict__ ht,
        const float* __restrict__ fc1_w,
        const float* __restrict__ fc1_b,
        const float* __restrict__ fc2_w,
        const float* __restrict__ fc2_b,
        float* __restrict__ out, int S) {
    const int tid  = threadIdx.x;
    const int lane = tid & 31;
    const int wid  = tid >> 5;
    const int bid  = blockIdx.x;

    // ------------------- HEAD block -------------------
    if (bid == 0) {
        if (wid == 0) {
            unsigned long long Rfull = g_seq_full;           // head-private
            unsigned epoch = (unsigned)((Rfull + 1ULL) & 0x7FFFULL);
            if (lane == 0) {
                unsigned target = (unsigned)((Rfull + 1ULL) << 8);  // 256*(R+1)
                while (*(volatile unsigned*)&g_count < target) { }
            }
            __syncwarp();
            __threadfence();                                 // acquire g_p
            const float4* gp4 = (const float4*)g_p;
            float4 p0 = __ldcg(gp4 + (lane << 1));
            float4 p1 = __ldcg(gp4 + (lane << 1) + 1);
            float v = ((p0.x + p0.y) + (p0.z + p0.w))
                    + ((p1.x + p1.y) + (p1.z + p1.w));
            #pragma unroll
            for (int o = 16; o > 0; o >>= 1)
                v += __shfl_down_sync(0xffffffffu, v, o);
            if (lane == 0) {
                double zd = (double)v + (double)fc2_b[0];
                // fast fp32 estimate -> publish immediately
                float zf  = (float)zd;
                float ptf = (float)S * __frcp_rn(1.0f + __expf(-zf));
                int est_lo = (int)ptf - ((WINDOW - 1) + PAD);
                if (est_lo < 0) est_lo = 0;
                *(volatile unsigned long long*)&g_est =
                    ((unsigned long long)epoch << 49)
                  | ((unsigned long long)(unsigned)est_lo << 32);
                // exact fp64 head (overlaps waiters' loads)
                double e  = fast_exp(-zd);
                double pt = (double)S * fast_recip(1.0 + e);
                int k = (int)pt;           // pt in (0,S), non-integer
                float et = __expf((float)(((double)S - pt) * (1.0 / 2048.0)));
                *(volatile unsigned long long*)&g_exact =
                    ((unsigned long long)epoch << 49)
                  | ((unsigned long long)(unsigned)k << 32)
                  | (unsigned long long)(unsigned)__float_as_int(et);
                g_seq_full = Rfull + 1ULL;
            }
        }
        return;
    }

    // ------------------- stage A: MLP row = bid-1 -------------------
    const int row = bid - 1;
    __shared__ float sred[8];
    __shared__ int   sh_est_lo;
    __shared__ int   sh_k;
    __shared__ float sh_et;

    float4 w = ((const float4*)(fc1_w + (size_t)row * HIDDEN))[tid];
    float4 h = ((const float4*)ht)[tid];
    double e0 = fma((double)w.y, (double)h.y, (double)w.x * h.x);
    double e1 = fma((double)w.w, (double)h.w, (double)w.z * h.z);
    float accf = (float)(e0 + e1);
    #pragma unroll
    for (int o = 16; o > 0; o >>= 1)
        accf += __shfl_down_sync(0xffffffffu, accf, o);
    if (lane == 0) sred[wid] = accf;
    __syncthreads();

    if (tid == 0) {
        // read epoch BEFORE our own increment (race-free)
        unsigned long long west = *(volatile unsigned long long*)&g_est;
        unsigned tgt = (unsigned)(((west >> 49) + 1ULL) & 0x7FFFULL);

        float zf = ((sred[0] + sred[1]) + (sred[2] + sred[3]))
                 + ((sred[4] + sred[5]) + (sred[6] + sred[7]))
                 + fc1_b[row];
        g_p[row] = tanhf(zf) * fc2_w[row];
        __threadfence();
        atomicAdd(&g_count, 1u);                 // REDG (return unused)

        // wait for the ESTIMATE publish
        do {
            west = *(volatile unsigned long long*)&g_est;
        } while ((unsigned)((west >> 49) & 0x7FFFULL) != tgt);
        sh_est_lo = (int)((west >> 32) & 0x1FFFFULL);
    }
    __syncthreads();

    // ------------- speculative padded window loads (issued now) -------------
    const int est_lo = sh_est_lo;
    const int col    = (row << 2) + (tid & 3);
    const int rowoff = tid >> 2;                 // 0..63
    const float* base = hs + col;
    const int r0 = est_lo + rowoff;
    const int r1 = r0 + 64;
    const int r2 = r0 + 128;

    float v0 = 0.f, v1 = 0.f, v2 = 0.f;
    if (r0 < S) v0 = base[(size_t)r0 * HIDDEN];
    if (r1 < S) v1 = base[(size_t)r1 * HIDDEN];
    if (r2 < S) v2 = base[(size_t)r2 * HIDDEN];

    // ------------- exact head (lands under the loads) -------------
    if (tid == 0) {
        unsigned long long west = *(volatile unsigned long long*)&g_est;
        unsigned tgt = (unsigned)((west >> 49) & 0x7FFFULL);  // current epoch
        unsigned long long wex;
        do {
            wex = *(volatile unsigned long long*)&g_exact;
        } while ((unsigned)((wex >> 49) & 0x7FFFULL) != tgt);
        sh_k  = (int)((wex >> 32) & 0x1FFFFULL);
        sh_et = __int_as_float((int)(unsigned)wex);
    }
    __syncthreads();

    const int k  = sh_k;
    int ws = k - (WINDOW - 1);  if (ws < 0)     ws = 0;
    int we = k + WINDOW;        if (we > S - 1) we = S - 1;
    const float et = sh_et;

    float acc = 0.f;
    if (r0 >= ws && r0 <= we) acc += v0;
    if (r1 >= ws && r1 <= we) acc += v1;
    if (r2 >= ws && r2 <= we) acc += v2;

    // fold the 8 rowgroups within each warp (keeps the 4 column lanes)
    #pragma unroll
    for (int o = 16; o >= 4; o >>= 1)
        acc += __shfl_xor_sync(0xffffffffu, acc, o);

    __shared__ float colsum[8][36];
    if (lane < 4) colsum[wid][lane] = acc;       // 8 warps x 4 cols
    __syncthreads();

    if (tid < 4) {
        float s = ((colsum[0][tid] + colsum[1][tid])
                 + (colsum[2][tid] + colsum[3][tid]))
                + ((colsum[4][tid] + colsum[5][tid])
                 + (colsum[6][tid] + colsum[7][tid]));
        out[col] = et * s;
    }
}

extern "C" void kernel_launch(void* const* d_in, const int* in_sizes, int n_in,
                              void* d_out, int out_size) {
    const float* hs    = (const float*)d_in[0];
    const float* ht    = (const float*)d_in[1];
    const float* fc1_w = (const float*)d_in[2];
    const float* fc1_b = (const float*)d_in[3];
    const float* fc2_w = (const float*)d_in[4];
    const float* fc2_b = (const float*)d_in[5];

    const int S = in_sizes[0] / HIDDEN;   // host-side constant, capture-safe

    fused_attn_kernel<<<NINTER + 1, 256>>>(hs, ht, fc1_w, fc1_b, fc2_w, fc2_b,
                                           (float*)d_out, S);
}

// round 13
// speedup vs baseline: 1.5814x; 1.1424x over previous
#include <cuda_runtime.h>
#include <math.h>

#define HIDDEN 1024
#define NINTER 256
#define WINDOW 64
#define PAD    8

#define CNT_SHIFT 55
#define FIX_BITS  46
#define FIX_SCALE 70368744177664.0f          // 2^46
#define FIX_BIAS  (1LL << FIX_BITS)          // per-term bias (keeps adds positive)

// persistent state (allocation-free rule: __device__ globals).
// g_acc is reset by the head block each replay (safe: replay N+1 cannot start
// until every block of replay N, including the head, has retired).
// g_seq_full is head-private; g_est/g_exact carry a 15-bit wrapping epoch.
__device__ unsigned long long g_acc;       // {count>=55 | biased fixed-point sum}
__device__ unsigned long long g_seq_full;
__device__ unsigned long long g_est;       // {epoch15<<49 | est_lo17<<32}
__device__ unsigned long long g_exact;     // {epoch15<<49 | k17<<32 | et_bits32}

// fp64 exp, rel err ~1e-13 (range reduction + degree-9, Estrin form)
__device__ __forceinline__ double fast_exp(double x) {
    const double LOG2E  = 1.4426950408889634074;
    const double LN2_HI = 6.9314718055994528623e-1;
    const double LN2_LO = 2.3190468138462995584e-17;
    double n = rint(x * LOG2E);
    double r = fma(-n, LN2_HI, x);
    r = fma(-n, LN2_LO, r);
    double p01 = 1.0 + r;
    double p23 = fma(r, 1.6666666666666665741e-1, 5.0e-1);
    double p45 = fma(r, 8.3333333333333332177e-3, 4.1666666666666664354e-2);
    double p67 = fma(r, 1.9841269841269841253e-4, 1.3888888888888889419e-3);
    double p89 = fma(r, 2.7557319223985890653e-6, 2.4801587301587301566e-5);
    double r2 = r * r;
    double q0 = fma(r2, p23, p01);
    double q1 = fma(r2, p67, p45);
    double r4 = r2 * r2;
    double s0 = fma(r4, q1, q0);
    double r8 = r4 * r4;
    double res = fma(r8, p89, s0);
    long long ni = (long long)n;
    double sc = __longlong_as_double((ni + 1023LL) << 52);  // exact 2^n
    return res * sc;
}

// 1/d via fp32 rcp seed + 1 fp64 Newton step (rel err ~2^-44)
__device__ __forceinline__ double fast_recip(double d) {
    double y = (double)__frcp_rn((float)d);
    return y * fma(-d, y, 2.0);
}

// ---------------------------------------------------------------------------
// ONE kernel, grid = 257 x 256.
// Blocks 1..256 (row = bid-1): MLP term -> ONE REDG.ADD.64 into g_acc, which
//   carries BOTH the completion count (bits >=55) and the exact biased
//   fixed-point sum (bits <55). Then poll g_est (estimate) -> issue padded
//   window loads -> poll g_exact (lands under the loads) -> mask -> reduce.
// Block 0 (head, single lane): poll g_acc count==256 -> sum is in the same
//   word -> publish fp32 ESTIMATE, then EXACT fp64 head, reset g_acc.
// Deadlock-free: waiters depend only on head publishes; head depends only on
// the 256 unconditional REDG adds. Waiters read the old epoch BEFORE their
// add (threadfence-ordered), so the head cannot publish before that read.
// ---------------------------------------------------------------------------
__global__ void __launch_bounds__(256) fused_attn_kernel(
        const float* __restrict__ hs,
        const float* __restrict__ ht,
        const float* __restrict__ fc1_w,
        const float* __restrict__ fc1_b,
        const float* __restrict__ fc2_w,
        const float* __restrict__ fc2_b,
        float* __restrict__ out, int S) {
    const int tid  = threadIdx.x;
    const int lane = tid & 31;
    const int wid  = tid >> 5;
    const int bid  = blockIdx.x;

    // ------------------- HEAD block (single lane) -------------------
    if (bid == 0) {
        if (tid == 0) {
            const float fb2 = fc2_b[0];                    // issue early
            unsigned long long Rfull = g_seq_full;
            unsigned epoch = (unsigned)((Rfull + 1ULL) & 0x7FFFULL);

            unsigned long long v;
            do {
                v = *(volatile unsigned long long*)&g_acc;
            } while ((v >> CNT_SHIFT) != (unsigned long long)NINTER);

            long long lows = (long long)(v & ((1ULL << CNT_SHIFT) - 1ULL));
            long long sum_fx = lows - ((long long)NINTER << FIX_BITS);
            double z = (double)sum_fx * (1.0 / (double)(1LL << FIX_BITS))
                     + (double)fb2;

            // fast fp32 estimate -> publish immediately
            float zf  = (float)z;
            float ptf = (float)S * __frcp_rn(1.0f + __expf(-zf));
            int est_lo = (int)ptf - ((WINDOW - 1) + PAD);
            if (est_lo < 0) est_lo = 0;
            *(volatile unsigned long long*)&g_est =
                ((unsigned long long)epoch << 49)
              | ((unsigned long long)(unsigned)est_lo << 32);

            // exact fp64 head (overlaps waiters' loads)
            double e  = fast_exp(-z);
            double pt = (double)S * fast_recip(1.0 + e);
            int k = (int)pt;                               // pt in (0,S)
            float et = __expf((float)(((double)S - pt) * (1.0 / 2048.0)));
            *(volatile unsigned long long*)&g_exact =
                ((unsigned long long)epoch << 49)
              | ((unsigned long long)(unsigned)k << 32)
              | (unsigned long long)(unsigned)__float_as_int(et);

            *(volatile unsigned long long*)&g_acc = 0ULL;  // reset for next replay
            g_seq_full = Rfull + 1ULL;
        }
        return;
    }

    // ------------------- stage A: MLP row = bid-1 -------------------
    const int row = bid - 1;
    __shared__ float sred[8];
    __shared__ int   sh_est_lo;
    __shared__ int   sh_k;
    __shared__ float sh_et;

    float4 w = ((const float4*)(fc1_w + (size_t)row * HIDDEN))[tid];
    float4 h = ((const float4*)ht)[tid];
    double e0 = fma((double)w.y, (double)h.y, (double)w.x * h.x);
    double e1 = fma((double)w.w, (double)h.w, (double)w.z * h.z);
    float accf = (float)(e0 + e1);
    #pragma unroll
    for (int o = 16; o > 0; o >>= 1)
        accf += __shfl_down_sync(0xffffffffu, accf, o);
    if (lane == 0) sred[wid] = accf;
    __syncthreads();

    if (tid == 0) {
        // read old epoch BEFORE our add (fence-ordered): race-free handshake
        unsigned long long west = *(volatile unsigned long long*)&g_est;
        unsigned old_ep = (unsigned)((west >> 49) & 0x7FFFULL);
        __threadfence();

        float zf = ((sred[0] + sred[1]) + (sred[2] + sred[3]))
                 + ((sred[4] + sred[5]) + (sred[6] + sred[7]))
                 + fc1_b[row];
        float term = tanhf(zf) * fc2_w[row];
        long long fx = __float2ll_rn(term * FIX_SCALE);    // exact in fixed point
        atomicAdd(&g_acc, (1ULL << CNT_SHIFT)
                          + (unsigned long long)(fx + FIX_BIAS));  // REDG.64

        // wait for the ESTIMATE publish (epoch change)
        do {
            west = *(volatile unsigned long long*)&g_est;
        } while ((unsigned)((west >> 49) & 0x7FFFULL) == old_ep);
        sh_est_lo = (int)((west >> 32) & 0x1FFFFULL);
    }
    __syncthreads();

    // ------------- speculative padded window loads (issued now) -------------
    const int est_lo = sh_est_lo;
    const int col    = (row << 2) + (tid & 3);
    const int rowoff = tid >> 2;                 // 0..63
    const float* base = hs + col;
    const int r0 = est_lo + rowoff;
    const int r1 = r0 + 64;
    const int r2 = r0 + 128;

    float v0 = 0.f, v1 = 0.f, v2 = 0.f;
    if (r0 < S) v0 = base[(size_t)r0 * HIDDEN];
    if (r1 < S) v1 = base[(size_t)r1 * HIDDEN];
    if (r2 < S) v2 = base[(size_t)r2 * HIDDEN];

    // ------------- exact head (lands under the loads) -------------
    if (tid == 0) {
        unsigned long long west = *(volatile unsigned long long*)&g_est;
        unsigned tgt = (unsigned)((west >> 49) & 0x7FFFULL);
        unsigned long long wex;
        do {
            wex = *(volatile unsigned long long*)&g_exact;
        } while ((unsigned)((wex >> 49) & 0x7FFFULL) != tgt);
        sh_k  = (int)((wex >> 32) & 0x1FFFFULL);
        sh_et = __int_as_float((int)(unsigned)wex);
    }
    __syncthreads();

    const int k  = sh_k;
    int ws = k - (WINDOW - 1);  if (ws < 0)     ws = 0;
    int we = k + WINDOW;        if (we > S - 1) we = S - 1;
    const float et = sh_et;

    float acc = 0.f;
    if (r0 >= ws && r0 <= we) acc += v0;
    if (r1 >= ws && r1 <= we) acc += v1;
    if (r2 >= ws && r2 <= we) acc += v2;

    // fold the 8 rowgroups within each warp (keeps the 4 column lanes)
    #pragma unroll
    for (int o = 16; o >= 4; o >>= 1)
        acc += __shfl_xor_sync(0xffffffffu, acc, o);

    __shared__ float colsum[8][36];
    if (lane < 4) colsum[wid][lane] = acc;       // 8 warps x 4 cols
    __syncthreads();

    if (tid < 4) {
        float s = ((colsum[0][tid] + colsum[1][tid])
                 + (colsum[2][tid] + colsum[3][tid]))
                + ((colsum[4][tid] + colsum[5][tid])
                 + (colsum[6][tid] + colsum[7][tid]));
        out[col] = et * s;
    }
}

extern "C" void kernel_launch(void* const* d_in, const int* in_sizes, int n_in,
                              void* d_out, int out_size) {
    const float* hs    = (const float*)d_in[0];
    const float* ht    = (const float*)d_in[1];
    const float* fc1_w = (const float*)d_in[2];
    const float* fc1_b = (const float*)d_in[3];
    const float* fc2_w = (const float*)d_in[4];
    const float* fc2_b = (const float*)d_in[5];

    const int S = in_sizes[0] / HIDDEN;   // host-side constant, capture-safe

    fused_attn_kernel<<<NINTER + 1, 256>>>(hs, ht, fc1_w, fc1_b, fc2_w, fc2_b,
                                           (float*)d_out, S);
}